// round 9
// baseline (speedup 1.0000x reference)
#include <cuda_runtime.h>

#define BATCH 64
#define T 128
#define N 32
#define M 8
#define P 16
#define MA 34    // padded row stride (even -> float2-aligned rows)
#define NCH 8    // backward-scan chunks
#define CHS 16   // chunk size

// ---- dynamic smem layout for k_fwd (floats) ----
#define F_A   0                       // [2 slots][2 buf][N*MA]
#define F_C   (F_A + 2*2*N*MA)        // [2][2][P*MA]
#define F_B   (F_C + 2*2*P*MA)        // [2][2][N*M]
#define F_V   (F_B + 2*2*N*M)         // [2][P*MA]
#define F_Z   (F_V + 2*P*MA)          // [2][P*MA]
#define F_CS  (F_Z + 2*P*MA)          // [2][P*MA]
#define F_SIG (F_CS + 2*P*MA)         // [2][N*MA]
#define F_AS  (F_SIG + 2*N*MA)        // [2][N*MA]
#define F_SP  (F_AS + 2*N*MA)         // [2][N*MA]
#define F_S   (F_SP + 2*N*MA)         // [2][P*18]
#define F_X   (F_S + 2*P*18)          // [2][P*MA]
#define F_Y   (F_X + 2*P*MA)          // [2][2][P]
#define F_U   (F_Y + 2*2*P)           // [2][2][M]
#define F_MU  (F_U + 2*2*M)           // [2][N]
#define F_MUP (F_MU + 2*N)            // [2][N]
#define F_D   (F_MUP + 2*N)           // [2][P]
#define F_TOT (F_D + 2*P)
#define SMEM_FWD_BYTES (F_TOT * 4)

// Global scratch
__device__ float g_muf[BATCH * T * N];
__device__ float g_mup[BATCH * T * N];
__device__ float g_Sigf[(size_t)BATCH * T * N * N];
__device__ float g_Sigp[(size_t)BATCH * T * N * N];
__device__ float g_J[(size_t)BATCH * (T - 1) * N * N];   // X_t = J_t^T
__device__ float g_M[(size_t)BATCH * (T - 1) * N * N];   // M_t
__device__ float g_c[(size_t)BATCH * (T - 1) * N];       // c_t
__device__ float g_OX[(size_t)BATCH * NCH * N * N];
__device__ float g_OM[(size_t)BATCH * NCH * N * N];
__device__ float g_Oc[(size_t)BATCH * NCH * N];
__device__ float g_eS[(size_t)BATCH * NCH * N * N];
__device__ float g_emu[(size_t)BATCH * NCH * N];

// =====================================================================
// Kernel 1: forward filter, TWO batch elements per CTA (latency interleave).
// grid = 32, block = 512. slot = tid>>8 handles batch 2*blockIdx+slot.
// Round-6 5-region pipeline per slot, retiled to 256 threads/slot.
// =====================================================================
extern __shared__ float dsm[];

__global__ __launch_bounds__(512, 1) void k_fwd(
    const float* __restrict__ Y, const float* __restrict__ U,
    const float* __restrict__ A, const float* __restrict__ Bm,
    const float* __restrict__ C, const float* __restrict__ mu0,
    const float* __restrict__ Sig0)
{
    const int tid = threadIdx.x;
    const int s = tid >> 8;       // slot 0/1
    const int lo = tid & 255;     // local thread id
    const int b = (blockIdx.x << 1) | s;

    float* pA0 = dsm + F_A + s * (2 * N * MA);            // +buf*N*MA
    float* pC0 = dsm + F_C + s * (2 * P * MA);
    float* pB0 = dsm + F_B + s * (2 * N * M);
    float* pV  = dsm + F_V + s * (P * MA);
    float* pZ  = dsm + F_Z + s * (P * MA);
    float* pCS = dsm + F_CS + s * (P * MA);
    float* pSg = dsm + F_SIG + s * (N * MA);
    float* pAS = dsm + F_AS + s * (N * MA);
    float* pSp = dsm + F_SP + s * (N * MA);
    float* pS  = dsm + F_S + s * (P * 18);
    float* pX  = dsm + F_X + s * (P * MA);
    float* py0 = dsm + F_Y + s * (2 * P);
    float* pu0 = dsm + F_U + s * (2 * M);
    float* pmu = dsm + F_MU + s * N;
    float* pmup = dsm + F_MUP + s * N;
    float* pd  = dsm + F_D + s * P;

    // ---- init: state + t=0 inputs ----
    if (lo < N) pmu[lo] = mu0[lo];
    for (int i2 = lo; i2 < 512; i2 += 256) {
        int r = i2 >> 4, c2 = i2 & 15;
        *(float2*)(pSg + r * MA + 2 * c2) = ((const float2*)Sig0)[i2];
    }
    {
        const size_t bt = (size_t)b * T;
        const float2* Ab = (const float2*)(A + bt * (N * N));
        const float2* Cb = (const float2*)(C + bt * (P * N));
        const float2* Bb = (const float2*)(Bm + bt * (N * M));
        for (int i2 = lo; i2 < 512; i2 += 256) {
            int r = i2 >> 4, c2 = i2 & 15;
            *(float2*)(pA0 + r * MA + 2 * c2) = Ab[i2];
        }
        if (lo < 256) {
            int r = lo >> 4, c2 = lo & 15;
            *(float2*)(pC0 + r * MA + 2 * c2) = Cb[lo];
        }
        if (lo < 128) ((float2*)pB0)[lo] = Bb[lo];
        if (lo < P) py0[lo] = Y[bt * P + lo];
        if (lo < M) pu0[lo] = U[bt * M + lo];
    }
    __syncthreads();

    for (int t = 0; t < T; t++) {
        const int cur = t & 1, nxt = cur ^ 1;
        const size_t bt = (size_t)b * T + t;
        const float* Ac = pA0 + cur * (N * MA);
        const float* Cc = pC0 + cur * (P * MA);
        const float* Bc = pB0 + cur * (N * M);
        const float* yc = py0 + cur * P;
        const float* uc = pu0 + cur * M;

        // ===== R0: AS = A*Sig (2x4, lo<128) | V = C*A (1x4) + mu_p =========
        if (lo < 128) {
            const int r0 = (lo >> 3) * 2, c0 = (lo & 7) * 4;
            const float2* Xr0 = (const float2*)(Ac + r0 * MA);
            const float2* Xr1 = (const float2*)(Ac + (r0 + 1) * MA);
            float a00 = 0, a01 = 0, a02 = 0, a03 = 0;
            float a10 = 0, a11 = 0, a12 = 0, a13 = 0;
            #pragma unroll
            for (int k2 = 0; k2 < 16; k2++) {
                float2 x0 = Xr0[k2], x1 = Xr1[k2];
                const float* y0p = pSg + (2 * k2) * MA + c0;
                const float* y1p = pSg + (2 * k2 + 1) * MA + c0;
                float2 y0a = *(const float2*)y0p, y0b = *(const float2*)(y0p + 2);
                float2 y1a = *(const float2*)y1p, y1b = *(const float2*)(y1p + 2);
                a00 += x0.x * y0a.x + x0.y * y1a.x;  a01 += x0.x * y0a.y + x0.y * y1a.y;
                a02 += x0.x * y0b.x + x0.y * y1b.x;  a03 += x0.x * y0b.y + x0.y * y1b.y;
                a10 += x1.x * y0a.x + x1.y * y1a.x;  a11 += x1.x * y0a.y + x1.y * y1a.y;
                a12 += x1.x * y0b.x + x1.y * y1b.x;  a13 += x1.x * y0b.y + x1.y * y1b.y;
            }
            *(float2*)(pAS + r0 * MA + c0) = make_float2(a00, a01);
            *(float2*)(pAS + r0 * MA + c0 + 2) = make_float2(a02, a03);
            *(float2*)(pAS + (r0 + 1) * MA + c0) = make_float2(a10, a11);
            *(float2*)(pAS + (r0 + 1) * MA + c0 + 2) = make_float2(a12, a13);
        } else {
            const int id = lo - 128;
            const int i = id >> 3, c0 = (id & 7) * 4;   // V: 16 rows x 8 quads
            const float2* Cr = (const float2*)(Cc + i * MA);
            float a0 = 0, a1 = 0, a2 = 0, a3 = 0;
            #pragma unroll
            for (int k2 = 0; k2 < 16; k2++) {
                float2 x = Cr[k2];
                const float* y0p = Ac + (2 * k2) * MA + c0;
                const float* y1p = Ac + (2 * k2 + 1) * MA + c0;
                float2 y0a = *(const float2*)y0p, y0b = *(const float2*)(y0p + 2);
                float2 y1a = *(const float2*)y1p, y1b = *(const float2*)(y1p + 2);
                a0 += x.x * y0a.x + x.y * y1a.x;  a1 += x.x * y0a.y + x.y * y1a.y;
                a2 += x.x * y0b.x + x.y * y1b.x;  a3 += x.x * y0b.y + x.y * y1b.y;
            }
            *(float2*)(pV + i * MA + c0) = make_float2(a0, a1);
            *(float2*)(pV + i * MA + c0 + 2) = make_float2(a2, a3);
            if (id < 32) {      // mu_p for state row id
                const float2* Ar = (const float2*)(Ac + id * MA);
                float sm = 0.f;
                #pragma unroll
                for (int j = 0; j < 16; j++) {
                    float2 a = Ar[j];
                    sm += a.x * pmu[2 * j] + a.y * pmu[2 * j + 1];
                }
                const float2* Br = (const float2*)(Bc + id * M);
                #pragma unroll
                for (int j = 0; j < 4; j++) {
                    float2 bb = Br[j];
                    sm += bb.x * uc[2 * j] + bb.y * uc[2 * j + 1];
                }
                pmup[id] = sm;
                g_mup[bt * N + id] = sm;
            }
        }
        __syncthreads();

        // ===== R1: Sig_p = AS*A^T + Q (2x4) | Z = V*Sig (1x4) ==============
        if (lo < 128) {
            const int r0 = (lo >> 3) * 2, c0 = (lo & 7) * 4;
            const float2* Xr0 = (const float2*)(pAS + r0 * MA);
            const float2* Xr1 = (const float2*)(pAS + (r0 + 1) * MA);
            const float2* Yc0 = (const float2*)(Ac + c0 * MA);
            const float2* Yc1 = (const float2*)(Ac + (c0 + 1) * MA);
            const float2* Yc2 = (const float2*)(Ac + (c0 + 2) * MA);
            const float2* Yc3 = (const float2*)(Ac + (c0 + 3) * MA);
            float a00 = 0, a01 = 0, a02 = 0, a03 = 0;
            float a10 = 0, a11 = 0, a12 = 0, a13 = 0;
            #pragma unroll
            for (int k2 = 0; k2 < 16; k2++) {
                float2 x0 = Xr0[k2], x1 = Xr1[k2];
                float2 y0 = Yc0[k2], y1 = Yc1[k2], y2 = Yc2[k2], y3 = Yc3[k2];
                a00 += x0.x * y0.x + x0.y * y0.y;  a01 += x0.x * y1.x + x0.y * y1.y;
                a02 += x0.x * y2.x + x0.y * y2.y;  a03 += x0.x * y3.x + x0.y * y3.y;
                a10 += x1.x * y0.x + x1.y * y0.y;  a11 += x1.x * y1.x + x1.y * y1.y;
                a12 += x1.x * y2.x + x1.y * y2.y;  a13 += x1.x * y3.x + x1.y * y3.y;
            }
            if (r0 == c0)          { a00 += 0.01f; a11 += 0.01f; }
            else if (r0 == c0 + 2) { a02 += 0.01f; a13 += 0.01f; }
            *(float2*)(pSp + r0 * MA + c0) = make_float2(a00, a01);
            *(float2*)(pSp + r0 * MA + c0 + 2) = make_float2(a02, a03);
            *(float2*)(pSp + (r0 + 1) * MA + c0) = make_float2(a10, a11);
            *(float2*)(pSp + (r0 + 1) * MA + c0 + 2) = make_float2(a12, a13);
        } else {
            const int id = lo - 128;
            const int i = id >> 3, c0 = (id & 7) * 4;   // Z: 16 x 32
            const float2* Vr = (const float2*)(pV + i * MA);
            float a0 = 0, a1 = 0, a2 = 0, a3 = 0;
            #pragma unroll
            for (int k2 = 0; k2 < 16; k2++) {
                float2 x = Vr[k2];
                const float* y0p = pSg + (2 * k2) * MA + c0;
                const float* y1p = pSg + (2 * k2 + 1) * MA + c0;
                float2 y0a = *(const float2*)y0p, y0b = *(const float2*)(y0p + 2);
                float2 y1a = *(const float2*)y1p, y1b = *(const float2*)(y1p + 2);
                a0 += x.x * y0a.x + x.y * y1a.x;  a1 += x.x * y0a.y + x.y * y1a.y;
                a2 += x.x * y0b.x + x.y * y1b.x;  a3 += x.x * y0b.y + x.y * y1b.y;
            }
            *(float2*)(pZ + i * MA + c0) = make_float2(a0, a1);
            *(float2*)(pZ + i * MA + c0 + 2) = make_float2(a2, a3);
        }
        __syncthreads();

        // ===== R2: CSp = Z*A^T+0.01C (1x4) | S = Z*V^T+0.01CC^T+R | d | STG =
        if (lo < 128) {
            const int i = lo >> 3, c0 = (lo & 7) * 4;
            const float2* Zr = (const float2*)(pZ + i * MA);
            const float2* Yc0 = (const float2*)(Ac + c0 * MA);
            const float2* Yc1 = (const float2*)(Ac + (c0 + 1) * MA);
            const float2* Yc2 = (const float2*)(Ac + (c0 + 2) * MA);
            const float2* Yc3 = (const float2*)(Ac + (c0 + 3) * MA);
            float2 cva = *(const float2*)(Cc + i * MA + c0);
            float2 cvb = *(const float2*)(Cc + i * MA + c0 + 2);
            float a0 = 0.01f * cva.x, a1 = 0.01f * cva.y;
            float a2 = 0.01f * cvb.x, a3 = 0.01f * cvb.y;
            #pragma unroll
            for (int k2 = 0; k2 < 16; k2++) {
                float2 x = Zr[k2];
                float2 y0 = Yc0[k2], y1 = Yc1[k2], y2 = Yc2[k2], y3 = Yc3[k2];
                a0 += x.x * y0.x + x.y * y0.y;  a1 += x.x * y1.x + x.y * y1.y;
                a2 += x.x * y2.x + x.y * y2.y;  a3 += x.x * y3.x + x.y * y3.y;
            }
            *(float2*)(pCS + i * MA + c0) = make_float2(a0, a1);
            *(float2*)(pCS + i * MA + c0 + 2) = make_float2(a2, a3);
        } else if (lo < 192) {
            const int id = lo - 128;                 // S: 16x16, 2x2 tiles
            const int i0 = (id >> 3) * 2, j0 = (id & 7) * 2;
            const float2* Zi0 = (const float2*)(pZ + i0 * MA);
            const float2* Zi1 = (const float2*)(pZ + (i0 + 1) * MA);
            const float2* Vj0 = (const float2*)(pV + j0 * MA);
            const float2* Vj1 = (const float2*)(pV + (j0 + 1) * MA);
            const float2* Ci0 = (const float2*)(Cc + i0 * MA);
            const float2* Ci1 = (const float2*)(Cc + (i0 + 1) * MA);
            const float2* Cj0 = (const float2*)(Cc + j0 * MA);
            const float2* Cj1 = (const float2*)(Cc + (j0 + 1) * MA);
            float a00 = (i0 == j0) ? 0.01f : 0.f, a01 = 0, a10 = 0;
            float a11 = (i0 == j0) ? 0.01f : 0.f;
            #pragma unroll
            for (int k2 = 0; k2 < 16; k2++) {
                float2 z0 = Zi0[k2], z1 = Zi1[k2];
                float2 v0 = Vj0[k2], v1 = Vj1[k2];
                float2 ci0 = Ci0[k2], ci1 = Ci1[k2];
                float2 cj0 = Cj0[k2], cj1 = Cj1[k2];
                a00 += z0.x * v0.x + z0.y * v0.y + 0.01f * (ci0.x * cj0.x + ci0.y * cj0.y);
                a01 += z0.x * v1.x + z0.y * v1.y + 0.01f * (ci0.x * cj1.x + ci0.y * cj1.y);
                a10 += z1.x * v0.x + z1.y * v0.y + 0.01f * (ci1.x * cj0.x + ci1.y * cj0.y);
                a11 += z1.x * v1.x + z1.y * v1.y + 0.01f * (ci1.x * cj1.x + ci1.y * cj1.y);
            }
            *(float2*)(pS + i0 * 18 + j0) = make_float2(a00, a01);
            *(float2*)(pS + (i0 + 1) * 18 + j0) = make_float2(a10, a11);
        } else if (lo < 208) {
            const int i = lo - 192;
            const float2* Cr = (const float2*)(Cc + i * MA);
            float sm = yc[i];
            #pragma unroll
            for (int j = 0; j < 16; j++) {
                float2 cv = Cr[j];
                sm -= cv.x * pmup[2 * j] + cv.y * pmup[2 * j + 1];
            }
            pd[i] = sm;
        } else {
            float2* gp = (float2*)(g_Sigp + (bt << 10));
            for (int i2 = lo - 208; i2 < 512; i2 += 48) {
                int rr = i2 >> 4, c2 = i2 & 15;
                gp[i2] = *(const float2*)(pSp + rr * MA + 2 * c2);
            }
        }
        __syncthreads();

        // ===== R3: per-slot warp solves S X = CSp | rest prefetch t+1 ======
        if (lo < 32) {
            const int c = lo;
            float Sc[P], Rc[P], piv[P];
            #pragma unroll
            for (int rr = 0; rr < P; rr++) {
                Sc[rr] = pS[rr * 18 + (c & 15)];
                Rc[rr] = pCS[rr * MA + c];
            }
            #pragma unroll
            for (int j = 0; j < P; j++) {
                float f[P];
                #pragma unroll
                for (int rr = 0; rr < P; rr++) f[rr] = __shfl_sync(0xffffffffu, Sc[rr], j);
                float pinv = 1.0f / f[j];
                piv[j] = f[j];
                float sj = Sc[j] * pinv, rj = Rc[j] * pinv;
                #pragma unroll
                for (int rr = 0; rr < P; rr++) {
                    if (rr != j) { Sc[rr] -= f[rr] * sj; Rc[rr] -= f[rr] * rj; }
                }
            }
            #pragma unroll
            for (int rr = 0; rr < P; rr++) pX[rr * MA + c] = Rc[rr] / piv[rr];
        } else if (t + 1 < T) {
            const int pt = lo - 32;    // 224 threads
            const size_t bt1 = bt + 1;
            float* An_s = pA0 + nxt * (N * MA);
            float* Cn_s = pC0 + nxt * (P * MA);
            float* Bn_s = pB0 + nxt * (N * M);
            const float2* An = (const float2*)(A + bt1 * (N * N));
            const float2* Cn = (const float2*)(C + bt1 * (P * N));
            const float2* Bn = (const float2*)(Bm + bt1 * (N * M));
            for (int i2 = pt; i2 < 512; i2 += 224) {
                int rr = i2 >> 4, c2 = i2 & 15;
                *(float2*)(An_s + rr * MA + 2 * c2) = An[i2];
            }
            for (int i2 = pt; i2 < 256; i2 += 224) {
                int rr = i2 >> 4, c2 = i2 & 15;
                *(float2*)(Cn_s + rr * MA + 2 * c2) = Cn[i2];
            }
            if (pt < 128) ((float2*)Bn_s)[pt] = Bn[pt];
            if (pt < P) py0[nxt * P + pt] = Y[bt1 * P + pt];
            else if (pt < P + M) pu0[nxt * M + (pt - P)] = U[bt1 * M + (pt - P)];
        }
        __syncthreads();

        // ===== R4: Sf = Sigp - 0.5*(X^T CSp + CSp^T X) (2x4) | mu_f ========
        if (lo < 128) {
            const int r0 = (lo >> 3) * 2, c0 = (lo & 7) * 4;
            float m00 = 0, m01 = 0, m02 = 0, m03 = 0;
            float m10 = 0, m11 = 0, m12 = 0, m13 = 0;
            #pragma unroll
            for (int j = 0; j < P; j++) {
                float2 xr = *(const float2*)(pX + j * MA + r0);
                float2 zr = *(const float2*)(pCS + j * MA + r0);
                const float* xcp = pX + j * MA + c0;
                const float* zcp = pCS + j * MA + c0;
                float2 xca = *(const float2*)xcp, xcb = *(const float2*)(xcp + 2);
                float2 zca = *(const float2*)zcp, zcb = *(const float2*)(zcp + 2);
                m00 += xr.x * zca.x + zr.x * xca.x;  m01 += xr.x * zca.y + zr.x * xca.y;
                m02 += xr.x * zcb.x + zr.x * xcb.x;  m03 += xr.x * zcb.y + zr.x * xcb.y;
                m10 += xr.y * zca.x + zr.y * xca.x;  m11 += xr.y * zca.y + zr.y * xca.y;
                m12 += xr.y * zcb.x + zr.y * xcb.x;  m13 += xr.y * zcb.y + zr.y * xcb.y;
            }
            const float* q0 = pSp + r0 * MA + c0;
            const float* q1 = pSp + (r0 + 1) * MA + c0;
            float2 p0a = *(const float2*)q0, p0b = *(const float2*)(q0 + 2);
            float2 p1a = *(const float2*)q1, p1b = *(const float2*)(q1 + 2);
            float v00 = p0a.x - 0.5f * m00, v01 = p0a.y - 0.5f * m01;
            float v02 = p0b.x - 0.5f * m02, v03 = p0b.y - 0.5f * m03;
            float v10 = p1a.x - 0.5f * m10, v11 = p1a.y - 0.5f * m11;
            float v12 = p1b.x - 0.5f * m12, v13 = p1b.y - 0.5f * m13;
            *(float2*)(pSg + r0 * MA + c0) = make_float2(v00, v01);
            *(float2*)(pSg + r0 * MA + c0 + 2) = make_float2(v02, v03);
            *(float2*)(pSg + (r0 + 1) * MA + c0) = make_float2(v10, v11);
            *(float2*)(pSg + (r0 + 1) * MA + c0 + 2) = make_float2(v12, v13);
            float* gf = g_Sigf + (bt << 10);
            *(float2*)(gf + r0 * 32 + c0) = make_float2(v00, v01);
            *(float2*)(gf + r0 * 32 + c0 + 2) = make_float2(v02, v03);
            *(float2*)(gf + (r0 + 1) * 32 + c0) = make_float2(v10, v11);
            *(float2*)(gf + (r0 + 1) * 32 + c0 + 2) = make_float2(v12, v13);
        } else if (lo < 160) {
            const int i = lo - 128;
            float sm = pmup[i];
            #pragma unroll
            for (int j = 0; j < P; j++) sm += pX[j * MA + i] * pd[j];
            pmu[i] = sm;
            g_muf[bt * N + i] = sm;
        }
        __syncthreads();
    }
}

// =====================================================================
// Kernel 2: per (b,t) compute X_t = J_t^T, M_t, c_t. grid (127, 64), 128 thr.
// =====================================================================
__global__ __launch_bounds__(128) void k_J2(const float* __restrict__ A)
{
    const int t = blockIdx.x;
    const int b = blockIdx.y;
    const size_t bt = (size_t)b * T + t;
    const int tid = threadIdx.x;

    __shared__ __align__(16) float sA[N * MA], sSf[N * MA], sSp[N * MA];
    __shared__ __align__(16) float sG[N * MA], sXs[N * MA];
    __shared__ float smf[N], smp[N];

    {
        const float2* Ab = (const float2*)(A + bt * (N * N));
        const float2* gf = (const float2*)(g_Sigf + (bt << 10));
        const float2* gp = (const float2*)(g_Sigp + ((bt + 1) << 10));
        for (int i2 = tid; i2 < 512; i2 += 128) {
            int r = i2 >> 4, c = (i2 & 15) * 2;
            *(float2*)(sA + r * MA + c) = Ab[i2];
            *(float2*)(sSf + r * MA + c) = gf[i2];
            *(float2*)(sSp + r * MA + c) = gp[i2];
        }
        if (tid < N) {
            smf[tid] = g_muf[bt * N + tid];
            smp[tid] = g_mup[(bt + 1) * N + tid];
        }
    }
    __syncthreads();

    #pragma unroll
    for (int s = 0; s < 2; s++) {
        const int id = tid + s * 128;
        const int r0 = (id >> 4) * 2, c0 = (id & 15) * 2;
        const float2* Xr0 = (const float2*)(sA + r0 * MA);
        const float2* Xr1 = (const float2*)(sA + (r0 + 1) * MA);
        float a00 = 0, a01 = 0, a10 = 0, a11 = 0;
        #pragma unroll
        for (int k2 = 0; k2 < 16; k2++) {
            float2 x0 = Xr0[k2], x1 = Xr1[k2];
            float2 y0 = *(const float2*)(sSf + (2 * k2) * MA + c0);
            float2 y1 = *(const float2*)(sSf + (2 * k2 + 1) * MA + c0);
            a00 += x0.x * y0.x + x0.y * y1.x;  a01 += x0.x * y0.y + x0.y * y1.y;
            a10 += x1.x * y0.x + x1.y * y1.x;  a11 += x1.x * y0.y + x1.y * y1.y;
        }
        *(float2*)(sG + r0 * MA + c0) = make_float2(a00, a01);
        *(float2*)(sG + (r0 + 1) * MA + c0) = make_float2(a10, a11);
    }
    __syncthreads();

    if (tid < 32) {
        const int c = tid;
        float Sc[N], Gc[N];
        #pragma unroll
        for (int rr = 0; rr < N; rr++) {
            Sc[rr] = sSp[rr * MA + c];
            Gc[rr] = sG[rr * MA + c];
        }
        #pragma unroll
        for (int j = 0; j < N; j++) {
            float fj = __shfl_sync(0xffffffffu, Sc[j], j);
            float pinv = 1.0f / fj;
            Sc[j] *= pinv;
            Gc[j] *= pinv;
            float scj = Sc[j], gcj = Gc[j];
            #pragma unroll
            for (int rr = 0; rr < N; rr++) {
                if (rr != j) {
                    float f = __shfl_sync(0xffffffffu, Sc[rr], j);
                    Sc[rr] -= f * scj;
                    Gc[rr] -= f * gcj;
                }
            }
        }
        #pragma unroll
        for (int rr = 0; rr < N; rr++) sXs[rr * MA + c] = Gc[rr];
    }
    __syncthreads();

    const size_t jidx = (size_t)b * (T - 1) + t;

    if (tid < N) {
        float s = smf[tid];
        #pragma unroll
        for (int k = 0; k < N; k++) s -= sXs[k * MA + tid] * smp[k];
        g_c[jidx * N + tid] = s;
    }
    {
        float2* gj = (float2*)(g_J + jidx * (N * N));
        for (int i2 = tid; i2 < 512; i2 += 128) {
            int r = i2 >> 4, c = (i2 & 15) * 2;
            gj[i2] = *(const float2*)(sXs + r * MA + c);
        }
    }
    {
        float* gm = g_M + jidx * (N * N);
        #pragma unroll
        for (int s = 0; s < 2; s++) {
            const int id = tid + s * 128;
            const int r0 = (id >> 4) * 2, c0 = (id & 15) * 2;
            float2 f0 = *(const float2*)(sSf + r0 * MA + c0);
            float2 f1 = *(const float2*)(sSf + (r0 + 1) * MA + c0);
            float a00 = f0.x, a01 = f0.y, a10 = f1.x, a11 = f1.y;
            #pragma unroll
            for (int k = 0; k < N; k++) {
                float x0 = sXs[k * MA + r0], x1 = sXs[k * MA + r0 + 1];
                float2 g = *(const float2*)(sG + k * MA + c0);
                a00 -= x0 * g.x;  a01 -= x0 * g.y;
                a10 -= x1 * g.x;  a11 -= x1 * g.y;
            }
            *(float2*)(gm + r0 * 32 + c0) = make_float2(a00, a01);
            *(float2*)(gm + (r0 + 1) * 32 + c0) = make_float2(a10, a11);
        }
    }
}

// =====================================================================
// Kernel 3 (Phase A): compose chunk operators. grid (8, 64), 256 thr.
// =====================================================================
__global__ __launch_bounds__(256) void k_scanA()
{
    const int k = blockIdx.x, b = blockIdx.y;
    const int t_lo = CHS * k;
    const int t_hi = (k == NCH - 1) ? (T - 2) : (CHS * k + CHS - 1);
    const int tid = threadIdx.x;

    __shared__ __align__(16) float sXO[N * MA], sMO[N * MA];
    __shared__ __align__(16) float sXt[2][N * MA], sMt[2][N * MA];
    __shared__ __align__(16) float sW[N * MA], sXN[N * MA];
    __shared__ float scO[N], sct[2][N], scN[N];

    const int r0 = (tid >> 4) * 2, c0 = (tid & 15) * 2;
    const int ra = tid >> 4, ca = (tid & 15) * 2;
    const int rb = ra + 16;

    {
        const size_t base = (size_t)b * (T - 1) + t_hi;
        const float2* gx = (const float2*)(g_J + base * (N * N));
        const float2* gm = (const float2*)(g_M + base * (N * N));
        for (int i2 = tid; i2 < 512; i2 += 256) {
            int r = i2 >> 4, c = (i2 & 15) * 2;
            *(float2*)(sXO + r * MA + c) = gx[i2];
            *(float2*)(sMO + r * MA + c) = gm[i2];
        }
        if (tid < N) scO[tid] = g_c[base * N + tid];
    }

    float2 pX0, pX1, pM0, pM1;
    float pc = 0.f;
    if (t_hi - 1 >= t_lo) {
        const size_t base = (size_t)b * (T - 1) + (t_hi - 1);
        const float2* gx = (const float2*)(g_J + base * (N * N));
        const float2* gm = (const float2*)(g_M + base * (N * N));
        pX0 = gx[tid];  pX1 = gx[tid + 256];
        pM0 = gm[tid];  pM1 = gm[tid + 256];
        if (tid < N) pc = g_c[base * N + tid];
    }
    __syncthreads();

    for (int t = t_hi - 1; t >= t_lo; t--) {
        const int buf = (t_hi - 1 - t) & 1;
        *(float2*)(sXt[buf] + ra * MA + ca) = pX0;
        *(float2*)(sXt[buf] + rb * MA + ca) = pX1;
        *(float2*)(sMt[buf] + ra * MA + ca) = pM0;
        *(float2*)(sMt[buf] + rb * MA + ca) = pM1;
        if (tid < N) sct[buf][tid] = pc;
        if (t > t_lo) {
            const size_t base = (size_t)b * (T - 1) + (t - 1);
            const float2* gx = (const float2*)(g_J + base * (N * N));
            const float2* gm = (const float2*)(g_M + base * (N * N));
            pX0 = gx[tid];  pX1 = gx[tid + 256];
            pM0 = gm[tid];  pM1 = gm[tid + 256];
            if (tid < N) pc = g_c[base * N + tid];
        }
        __syncthreads();

        const float* Xt = sXt[buf];
        const float* Mt = sMt[buf];

        {
            const float2* Mr0 = (const float2*)(sMO + r0 * MA);
            const float2* Mr1 = (const float2*)(sMO + (r0 + 1) * MA);
            const float2* Or0 = (const float2*)(sXO + r0 * MA);
            const float2* Or1 = (const float2*)(sXO + (r0 + 1) * MA);
            float w00 = 0, w01 = 0, w10 = 0, w11 = 0;
            float x00 = 0, x01 = 0, x10 = 0, x11 = 0;
            #pragma unroll
            for (int k2 = 0; k2 < 16; k2++) {
                float2 y0 = *(const float2*)(Xt + (2 * k2) * MA + c0);
                float2 y1 = *(const float2*)(Xt + (2 * k2 + 1) * MA + c0);
                float2 m0 = Mr0[k2], m1 = Mr1[k2];
                float2 o0 = Or0[k2], o1 = Or1[k2];
                w00 += m0.x * y0.x + m0.y * y1.x;  w01 += m0.x * y0.y + m0.y * y1.y;
                w10 += m1.x * y0.x + m1.y * y1.x;  w11 += m1.x * y0.y + m1.y * y1.y;
                x00 += o0.x * y0.x + o0.y * y1.x;  x01 += o0.x * y0.y + o0.y * y1.y;
                x10 += o1.x * y0.x + o1.y * y1.x;  x11 += o1.x * y0.y + o1.y * y1.y;
            }
            *(float2*)(sW + r0 * MA + c0) = make_float2(w00, w01);
            *(float2*)(sW + (r0 + 1) * MA + c0) = make_float2(w10, w11);
            *(float2*)(sXN + r0 * MA + c0) = make_float2(x00, x01);
            *(float2*)(sXN + (r0 + 1) * MA + c0) = make_float2(x10, x11);
        }
        if (tid < N) {
            float s = sct[buf][tid];
            #pragma unroll
            for (int j = 0; j < N; j++) s += Xt[j * MA + tid] * scO[j];
            scN[tid] = s;
        }
        __syncthreads();

        {
            float2 f0 = *(const float2*)(Mt + r0 * MA + c0);
            float2 f1 = *(const float2*)(Mt + (r0 + 1) * MA + c0);
            float a00 = f0.x, a01 = f0.y, a10 = f1.x, a11 = f1.y;
            #pragma unroll
            for (int j = 0; j < N; j++) {
                float2 xj = *(const float2*)(Xt + j * MA + r0);
                float2 wj = *(const float2*)(sW + j * MA + c0);
                a00 += xj.x * wj.x;  a01 += xj.x * wj.y;
                a10 += xj.y * wj.x;  a11 += xj.y * wj.y;
            }
            *(float2*)(sMO + r0 * MA + c0) = make_float2(a00, a01);
            *(float2*)(sMO + (r0 + 1) * MA + c0) = make_float2(a10, a11);
            *(float2*)(sXO + r0 * MA + c0) = *(const float2*)(sXN + r0 * MA + c0);
            *(float2*)(sXO + (r0 + 1) * MA + c0) = *(const float2*)(sXN + (r0 + 1) * MA + c0);
        }
        if (tid < N) scO[tid] = scN[tid];
        __syncthreads();
    }

    {
        const size_t obase = (size_t)b * NCH + k;
        float2* gx = (float2*)(g_OX + obase * (N * N));
        float2* gm = (float2*)(g_OM + obase * (N * N));
        for (int i2 = tid; i2 < 512; i2 += 256) {
            int r = i2 >> 4, c = (i2 & 15) * 2;
            gx[i2] = *(const float2*)(sXO + r * MA + c);
            gm[i2] = *(const float2*)(sMO + r * MA + c);
        }
        if (tid < N) g_Oc[obase * N + tid] = scO[tid];
    }
}

// =====================================================================
// Kernel 4 (Phase B): boundary states per batch. grid 64, 256 thr.
// =====================================================================
__global__ __launch_bounds__(256) void k_scanB(float* __restrict__ out)
{
    const int b = blockIdx.x;
    const int tid = threadIdx.x;

    __shared__ __align__(16) float sS[N * MA], sX[N * MA], sMm[N * MA], sW[N * MA];
    __shared__ float smu[N], smuN[N], sc[N];

    const int r0 = (tid >> 4) * 2, c0 = (tid & 15) * 2;

    {
        const size_t btL = (size_t)b * T + (T - 1);
        const float2* gf = (const float2*)(g_Sigf + (btL << 10));
        float2* ge = (float2*)(g_eS + ((size_t)b * NCH + (NCH - 1)) * (N * N));
        for (int i2 = tid; i2 < 512; i2 += 256) {
            int r = i2 >> 4, c = (i2 & 15) * 2;
            float2 v = gf[i2];
            *(float2*)(sS + r * MA + c) = v;
            ge[i2] = v;
            float* o = out + (btL * N + r) * (N + 1) + 1 + c;
            o[0] = v.x; o[1] = v.y;
        }
        if (tid < N) {
            float v = g_muf[btL * N + tid];
            smu[tid] = v;
            g_emu[((size_t)b * NCH + (NCH - 1)) * N + tid] = v;
            out[(btL * N + tid) * (N + 1)] = v;
        }
    }
    __syncthreads();

    for (int k = NCH - 2; k >= 0; k--) {
        const size_t obase = (size_t)b * NCH + (k + 1);
        {
            const float2* gx = (const float2*)(g_OX + obase * (N * N));
            const float2* gm = (const float2*)(g_OM + obase * (N * N));
            for (int i2 = tid; i2 < 512; i2 += 256) {
                int r = i2 >> 4, c = (i2 & 15) * 2;
                *(float2*)(sX + r * MA + c) = gx[i2];
                *(float2*)(sMm + r * MA + c) = gm[i2];
            }
            if (tid < N) sc[tid] = g_Oc[obase * N + tid];
        }
        __syncthreads();

        {
            const float2* Sr0 = (const float2*)(sS + r0 * MA);
            const float2* Sr1 = (const float2*)(sS + (r0 + 1) * MA);
            float a00 = 0, a01 = 0, a10 = 0, a11 = 0;
            #pragma unroll
            for (int k2 = 0; k2 < 16; k2++) {
                float2 x0 = Sr0[k2], x1 = Sr1[k2];
                float2 y0 = *(const float2*)(sX + (2 * k2) * MA + c0);
                float2 y1 = *(const float2*)(sX + (2 * k2 + 1) * MA + c0);
                a00 += x0.x * y0.x + x0.y * y1.x;  a01 += x0.x * y0.y + x0.y * y1.y;
                a10 += x1.x * y0.x + x1.y * y1.x;  a11 += x1.x * y0.y + x1.y * y1.y;
            }
            *(float2*)(sW + r0 * MA + c0) = make_float2(a00, a01);
            *(float2*)(sW + (r0 + 1) * MA + c0) = make_float2(a10, a11);
        }
        if (tid < N) {
            float s = sc[tid];
            #pragma unroll
            for (int j = 0; j < N; j++) s += sX[j * MA + tid] * smu[j];
            smuN[tid] = s;
        }
        __syncthreads();

        {
            float2 f0 = *(const float2*)(sMm + r0 * MA + c0);
            float2 f1 = *(const float2*)(sMm + (r0 + 1) * MA + c0);
            float a00 = f0.x, a01 = f0.y, a10 = f1.x, a11 = f1.y;
            #pragma unroll
            for (int j = 0; j < N; j++) {
                float2 xj = *(const float2*)(sX + j * MA + r0);
                float2 wj = *(const float2*)(sW + j * MA + c0);
                a00 += xj.x * wj.x;  a01 += xj.x * wj.y;
                a10 += xj.y * wj.x;  a11 += xj.y * wj.y;
            }
            *(float2*)(sS + r0 * MA + c0) = make_float2(a00, a01);
            *(float2*)(sS + (r0 + 1) * MA + c0) = make_float2(a10, a11);
            float* ge = g_eS + ((size_t)b * NCH + k) * (N * N);
            *(float2*)(ge + r0 * 32 + c0) = make_float2(a00, a01);
            *(float2*)(ge + (r0 + 1) * 32 + c0) = make_float2(a10, a11);
        }
        if (tid < N) {
            smu[tid] = smuN[tid];
            g_emu[((size_t)b * NCH + k) * N + tid] = smuN[tid];
        }
        __syncthreads();
    }
}

// =====================================================================
// Kernel 5 (Phase C): per-chunk backward recursion. grid (8, 64), 256 thr.
// =====================================================================
__global__ __launch_bounds__(256) void k_scanC(float* __restrict__ out)
{
    const int k = blockIdx.x, b = blockIdx.y;
    const int t_lo = CHS * k;
    const int t_hi = (k == NCH - 1) ? (T - 2) : (CHS * k + CHS - 1);
    const int tid = threadIdx.x;

    __shared__ __align__(16) float sS[N * MA], sW[N * MA];
    __shared__ __align__(16) float sX[2][N * MA], sMm[2][N * MA];
    __shared__ float smu[N], smuN[N], sc[2][N];

    const int r0 = (tid >> 4) * 2, c0 = (tid & 15) * 2;
    const int ra = tid >> 4, ca = (tid & 15) * 2;
    const int rb = ra + 16;

    {
        const size_t ebase = (size_t)b * NCH + k;
        const float2* ge = (const float2*)(g_eS + ebase * (N * N));
        for (int i2 = tid; i2 < 512; i2 += 256) {
            int r = i2 >> 4, c = (i2 & 15) * 2;
            *(float2*)(sS + r * MA + c) = ge[i2];
        }
        if (tid < N) smu[tid] = g_emu[ebase * N + tid];
    }

    float2 pX0, pX1, pM0, pM1;
    float pc = 0.f;
    {
        const size_t base = (size_t)b * (T - 1) + t_hi;
        const float2* gx = (const float2*)(g_J + base * (N * N));
        const float2* gm = (const float2*)(g_M + base * (N * N));
        pX0 = gx[tid];  pX1 = gx[tid + 256];
        pM0 = gm[tid];  pM1 = gm[tid + 256];
        if (tid < N) pc = g_c[base * N + tid];
    }
    __syncthreads();

    for (int t = t_hi; t >= t_lo; t--) {
        const int buf = (t_hi - t) & 1;
        const size_t bt = (size_t)b * T + t;
        *(float2*)(sX[buf] + ra * MA + ca) = pX0;
        *(float2*)(sX[buf] + rb * MA + ca) = pX1;
        *(float2*)(sMm[buf] + ra * MA + ca) = pM0;
        *(float2*)(sMm[buf] + rb * MA + ca) = pM1;
        if (tid < N) sc[buf][tid] = pc;
        if (t > t_lo) {
            const size_t base = (size_t)b * (T - 1) + (t - 1);
            const float2* gx = (const float2*)(g_J + base * (N * N));
            const float2* gm = (const float2*)(g_M + base * (N * N));
            pX0 = gx[tid];  pX1 = gx[tid + 256];
            pM0 = gm[tid];  pM1 = gm[tid + 256];
            if (tid < N) pc = g_c[base * N + tid];
        }
        __syncthreads();

        const float* Xb = sX[buf];
        const float* Mb = sMm[buf];

        {
            const float2* Sr0 = (const float2*)(sS + r0 * MA);
            const float2* Sr1 = (const float2*)(sS + (r0 + 1) * MA);
            float a00 = 0, a01 = 0, a10 = 0, a11 = 0;
            #pragma unroll
            for (int k2 = 0; k2 < 16; k2++) {
                float2 x0 = Sr0[k2], x1 = Sr1[k2];
                float2 y0 = *(const float2*)(Xb + (2 * k2) * MA + c0);
                float2 y1 = *(const float2*)(Xb + (2 * k2 + 1) * MA + c0);
                a00 += x0.x * y0.x + x0.y * y1.x;  a01 += x0.x * y0.y + x0.y * y1.y;
                a10 += x1.x * y0.x + x1.y * y1.x;  a11 += x1.x * y0.y + x1.y * y1.y;
            }
            *(float2*)(sW + r0 * MA + c0) = make_float2(a00, a01);
            *(float2*)(sW + (r0 + 1) * MA + c0) = make_float2(a10, a11);
        }
        if (tid < N) {
            float s = sc[buf][tid];
            #pragma unroll
            for (int j = 0; j < N; j++) s += Xb[j * MA + tid] * smu[j];
            smuN[tid] = s;
        }
        __syncthreads();

        {
            float2 f0 = *(const float2*)(Mb + r0 * MA + c0);
            float2 f1 = *(const float2*)(Mb + (r0 + 1) * MA + c0);
            float a00 = f0.x, a01 = f0.y, a10 = f1.x, a11 = f1.y;
            #pragma unroll
            for (int j = 0; j < N; j++) {
                float2 xj = *(const float2*)(Xb + j * MA + r0);
                float2 wj = *(const float2*)(sW + j * MA + c0);
                a00 += xj.x * wj.x;  a01 += xj.x * wj.y;
                a10 += xj.y * wj.x;  a11 += xj.y * wj.y;
            }
            *(float2*)(sS + r0 * MA + c0) = make_float2(a00, a01);
            *(float2*)(sS + (r0 + 1) * MA + c0) = make_float2(a10, a11);
            float* o = out + (bt * N + r0) * (N + 1) + 1 + c0;
            o[0] = a00; o[1] = a01;
            o[N + 1] = a10; o[N + 2] = a11;
        }
        if (tid < N) {
            smu[tid] = smuN[tid];
            out[(bt * N + tid) * (N + 1)] = smuN[tid];
        }
        __syncthreads();
    }
}

extern "C" void kernel_launch(void* const* d_in, const int* in_sizes, int n_in,
                              void* d_out, int out_size) {
    (void)in_sizes; (void)n_in; (void)out_size;
    const float* Y   = (const float*)d_in[0];
    const float* U   = (const float*)d_in[1];
    const float* A   = (const float*)d_in[2];
    const float* Bm  = (const float*)d_in[3];
    const float* C   = (const float*)d_in[4];
    const float* mu0 = (const float*)d_in[5];
    const float* S0  = (const float*)d_in[6];
    float* out = (float*)d_out;

    static int attr_set = 0;
    if (!attr_set) {
        cudaFuncSetAttribute(k_fwd, cudaFuncAttributeMaxDynamicSharedMemorySize,
                             SMEM_FWD_BYTES);
        attr_set = 1;
    }

    k_fwd<<<BATCH / 2, 512, SMEM_FWD_BYTES>>>(Y, U, A, Bm, C, mu0, S0);
    k_J2<<<dim3(T - 1, BATCH), 128>>>(A);
    k_scanA<<<dim3(NCH, BATCH), 256>>>();
    k_scanB<<<BATCH, 256>>>(out);
    k_scanC<<<dim3(NCH, BATCH), 256>>>(out);
}

// round 10
// speedup vs baseline: 1.5144x; 1.5144x over previous
#include <cuda_runtime.h>

#define BATCH 64
#define T 128
#define N 32
#define M 8
#define P 16
#define MA 34    // padded row stride (even -> float2-aligned rows)
#define NCH 16   // backward-scan chunks
#define CHS 8    // chunk size
#define NTF 512  // k_fwd threads

// Global scratch
__device__ float g_muf[BATCH * T * N];
__device__ float g_mup[BATCH * T * N];
__device__ float g_Sigf[(size_t)BATCH * T * N * N];
__device__ float g_Sigp[(size_t)BATCH * T * N * N];
__device__ float g_J[(size_t)BATCH * (T - 1) * N * N];   // X_t = J_t^T
__device__ float g_M[(size_t)BATCH * (T - 1) * N * N];   // M_t
__device__ float g_c[(size_t)BATCH * (T - 1) * N];       // c_t
__device__ float g_OX[(size_t)BATCH * NCH * N * N];
__device__ float g_OM[(size_t)BATCH * NCH * N * N];
__device__ float g_Oc[(size_t)BATCH * NCH * N];
__device__ float g_eS[(size_t)BATCH * NCH * N * N];
__device__ float g_emu[(size_t)BATCH * NCH * N];

// =====================================================================
// Kernel 1: forward Kalman filter (proven 1011.8 config, verbatim).
// One CTA (512 thr) per batch element; 5 regions/step with V=C*A trick.
// =====================================================================
__global__ __launch_bounds__(NTF, 1) void k_fwd(
    const float* __restrict__ Y, const float* __restrict__ U,
    const float* __restrict__ A, const float* __restrict__ Bm,
    const float* __restrict__ C, const float* __restrict__ mu0,
    const float* __restrict__ Sig0)
{
    const int b = blockIdx.x;
    const int tid = threadIdx.x;

    __shared__ __align__(16) float sA[2][N * MA];
    __shared__ __align__(16) float sC[2][P * MA];
    __shared__ __align__(16) float sB[2][N * M];
    __shared__ float sy[2][P], su[2][M];
    __shared__ __align__(16) float sSig[N * MA], sAS[N * MA], sSigp[N * MA];
    __shared__ __align__(16) float sV[P * MA], sZ[P * MA], sCSp[P * MA];
    __shared__ __align__(16) float sS[P * 18];
    __shared__ __align__(16) float sX[P * MA];     // X = K^T (16 x 32)
    __shared__ float smu[N], smup[N], sd[P];

    // ---- init state + t=0 inputs ----
    if (tid < N) smu[tid] = mu0[tid];
    for (int i2 = tid; i2 < 512; i2 += NTF) {
        int r = i2 >> 4, c2 = i2 & 15;
        *(float2*)(sSig + r * MA + 2 * c2) = ((const float2*)Sig0)[i2];
    }
    {
        const size_t bt = (size_t)b * T;
        const float2* Ab = (const float2*)(A + bt * (N * N));
        const float2* Cb = (const float2*)(C + bt * (P * N));
        const float2* Bb = (const float2*)(Bm + bt * (N * M));
        for (int i2 = tid; i2 < 512; i2 += NTF) {
            int r = i2 >> 4, c2 = i2 & 15;
            *(float2*)(sA[0] + r * MA + 2 * c2) = Ab[i2];
        }
        if (tid < 256) {
            int r = tid >> 4, c2 = tid & 15;
            *(float2*)(sC[0] + r * MA + 2 * c2) = Cb[tid];
        }
        if (tid < 128) ((float2*)sB[0])[tid] = Bb[tid];
        if (tid < P) sy[0][tid] = Y[bt * P + tid];
        if (tid < M) su[0][tid] = U[bt * M + tid];
    }
    __syncthreads();

    for (int t = 0; t < T; t++) {
        const int cur = t & 1, nxt = cur ^ 1;
        const size_t bt = (size_t)b * T + t;
        const float* Ac = sA[cur];
        const float* Cc = sC[cur];

        // ================= R0: AS = A*Sig (2x2) | V = C*A (1x2) + mu_p ======
        if (tid < 256) {
            const int r0 = (tid >> 4) * 2, c0 = (tid & 15) * 2;
            const float2* Xr0 = (const float2*)(Ac + r0 * MA);
            const float2* Xr1 = (const float2*)(Ac + (r0 + 1) * MA);
            float a00 = 0, a01 = 0, a10 = 0, a11 = 0;
            #pragma unroll
            for (int k2 = 0; k2 < 16; k2++) {
                float2 x0 = Xr0[k2], x1 = Xr1[k2];
                float2 y0 = *(const float2*)(sSig + (2 * k2) * MA + c0);
                float2 y1 = *(const float2*)(sSig + (2 * k2 + 1) * MA + c0);
                a00 += x0.x * y0.x + x0.y * y1.x;  a01 += x0.x * y0.y + x0.y * y1.y;
                a10 += x1.x * y0.x + x1.y * y1.x;  a11 += x1.x * y0.y + x1.y * y1.y;
            }
            *(float2*)(sAS + r0 * MA + c0) = make_float2(a00, a01);
            *(float2*)(sAS + (r0 + 1) * MA + c0) = make_float2(a10, a11);
        } else {
            const int id = tid - 256;
            const int i = id >> 4, j0 = (id & 15) * 2;
            const float2* Cr = (const float2*)(Cc + i * MA);
            float a0 = 0, a1 = 0;
            #pragma unroll
            for (int k2 = 0; k2 < 16; k2++) {
                float2 cv = Cr[k2];
                float2 y0 = *(const float2*)(Ac + (2 * k2) * MA + j0);
                float2 y1 = *(const float2*)(Ac + (2 * k2 + 1) * MA + j0);
                a0 += cv.x * y0.x + cv.y * y1.x;
                a1 += cv.x * y0.y + cv.y * y1.y;
            }
            *(float2*)(sV + i * MA + j0) = make_float2(a0, a1);
            if (id < 32) {      // mu_p for state row id
                const float2* Ar = (const float2*)(Ac + id * MA);
                float s = 0.f;
                #pragma unroll
                for (int j = 0; j < 16; j++) {
                    float2 a = Ar[j];
                    s += a.x * smu[2 * j] + a.y * smu[2 * j + 1];
                }
                const float2* Br = (const float2*)(sB[cur] + id * M);
                #pragma unroll
                for (int j = 0; j < 4; j++) {
                    float2 bb = Br[j];
                    s += bb.x * su[cur][2 * j] + bb.y * su[cur][2 * j + 1];
                }
                smup[id] = s;
                g_mup[bt * N + id] = s;
            }
        }
        __syncthreads();

        // ================= R1: Sig_p = AS*A^T + Q (2x2) | Z = V*Sig (1x2) ===
        if (tid < 256) {
            const int r0 = (tid >> 4) * 2, c0 = (tid & 15) * 2;
            const float2* Xr0 = (const float2*)(sAS + r0 * MA);
            const float2* Xr1 = (const float2*)(sAS + (r0 + 1) * MA);
            const float2* Yc0 = (const float2*)(Ac + c0 * MA);
            const float2* Yc1 = (const float2*)(Ac + (c0 + 1) * MA);
            float a00 = (r0 == c0) ? 0.01f : 0.f, a01 = 0, a10 = 0;
            float a11 = (r0 == c0) ? 0.01f : 0.f;
            #pragma unroll
            for (int k2 = 0; k2 < 16; k2++) {
                float2 x0 = Xr0[k2], x1 = Xr1[k2], y0 = Yc0[k2], y1 = Yc1[k2];
                a00 += x0.x * y0.x + x0.y * y0.y;  a01 += x0.x * y1.x + x0.y * y1.y;
                a10 += x1.x * y0.x + x1.y * y0.y;  a11 += x1.x * y1.x + x1.y * y1.y;
            }
            *(float2*)(sSigp + r0 * MA + c0) = make_float2(a00, a01);
            *(float2*)(sSigp + (r0 + 1) * MA + c0) = make_float2(a10, a11);
        } else {
            const int id = tid - 256;
            const int i = id >> 4, j0 = (id & 15) * 2;
            const float2* Vr = (const float2*)(sV + i * MA);
            float a0 = 0, a1 = 0;
            #pragma unroll
            for (int k2 = 0; k2 < 16; k2++) {
                float2 v = Vr[k2];
                float2 y0 = *(const float2*)(sSig + (2 * k2) * MA + j0);
                float2 y1 = *(const float2*)(sSig + (2 * k2 + 1) * MA + j0);
                a0 += v.x * y0.x + v.y * y1.x;
                a1 += v.x * y0.y + v.y * y1.y;
            }
            *(float2*)(sZ + i * MA + j0) = make_float2(a0, a1);
        }
        __syncthreads();

        // ==== R2: CSp = Z*A^T + 0.01C | S = Z*V^T + 0.01CC^T + R | resid | STG Sig_p
        if (tid < 256) {
            const int i = tid >> 4, j0 = (tid & 15) * 2;
            const float2* Zr = (const float2*)(sZ + i * MA);
            const float2* Aj0 = (const float2*)(Ac + j0 * MA);
            const float2* Aj1 = (const float2*)(Ac + (j0 + 1) * MA);
            float2 cv = *(const float2*)(Cc + i * MA + j0);
            float a0 = 0.01f * cv.x, a1 = 0.01f * cv.y;
            #pragma unroll
            for (int k2 = 0; k2 < 16; k2++) {
                float2 z = Zr[k2], y0 = Aj0[k2], y1 = Aj1[k2];
                a0 += z.x * y0.x + z.y * y0.y;
                a1 += z.x * y1.x + z.y * y1.y;
            }
            *(float2*)(sCSp + i * MA + j0) = make_float2(a0, a1);
        } else if (tid < 384) {
            const int id = tid - 256;
            const int i = id >> 3, j0 = (id & 7) * 2;
            const float2* Zr = (const float2*)(sZ + i * MA);
            const float2* Ci = (const float2*)(Cc + i * MA);
            const float2* Vj0 = (const float2*)(sV + j0 * MA);
            const float2* Vj1 = (const float2*)(sV + (j0 + 1) * MA);
            const float2* Cj0 = (const float2*)(Cc + j0 * MA);
            const float2* Cj1 = (const float2*)(Cc + (j0 + 1) * MA);
            float a0 = (i == j0) ? 0.01f : 0.f;
            float a1 = (i == j0 + 1) ? 0.01f : 0.f;
            #pragma unroll
            for (int k2 = 0; k2 < 16; k2++) {
                float2 z = Zr[k2], ci = Ci[k2];
                float2 v0 = Vj0[k2], v1 = Vj1[k2];
                float2 c0v = Cj0[k2], c1v = Cj1[k2];
                a0 += z.x * v0.x + z.y * v0.y + 0.01f * (ci.x * c0v.x + ci.y * c0v.y);
                a1 += z.x * v1.x + z.y * v1.y + 0.01f * (ci.x * c1v.x + ci.y * c1v.y);
            }
            *(float2*)(sS + i * 18 + j0) = make_float2(a0, a1);
        } else if (tid < 400) {
            const int i = tid - 384;
            const float2* Cr = (const float2*)(Cc + i * MA);
            float s = sy[cur][i];
            #pragma unroll
            for (int j = 0; j < 16; j++) {
                float2 cv = Cr[j];
                s -= cv.x * smup[2 * j] + cv.y * smup[2 * j + 1];
            }
            sd[i] = s;
        } else {
            float2* gp = (float2*)(g_Sigp + (bt << 10));
            for (int i2 = tid - 400; i2 < 512; i2 += 112) {
                int rr = i2 >> 4, c2 = i2 & 15;
                gp[i2] = *(const float2*)(sSigp + rr * MA + 2 * c2);
            }
        }
        __syncthreads();

        // ================= R3: warp0 solves S X = CSp | others prefetch t+1 =
        if (tid < 32) {
            const int c = tid;
            float Sc[P], Rc[P], piv[P];
            #pragma unroll
            for (int rr = 0; rr < P; rr++) {
                Sc[rr] = sS[rr * 18 + (c & 15)];
                Rc[rr] = sCSp[rr * MA + c];
            }
            #pragma unroll
            for (int j = 0; j < P; j++) {
                float f[P];
                #pragma unroll
                for (int rr = 0; rr < P; rr++) f[rr] = __shfl_sync(0xffffffffu, Sc[rr], j);
                float pinv = 1.0f / f[j];
                piv[j] = f[j];
                float sj = Sc[j] * pinv, rj = Rc[j] * pinv;
                #pragma unroll
                for (int rr = 0; rr < P; rr++) {
                    if (rr != j) { Sc[rr] -= f[rr] * sj; Rc[rr] -= f[rr] * rj; }
                }
            }
            #pragma unroll
            for (int rr = 0; rr < P; rr++) sX[rr * MA + c] = Rc[rr] / piv[rr];
        } else if (t + 1 < T) {
            const int pt = tid - 32;
            const size_t bt1 = bt + 1;
            const float2* An = (const float2*)(A + bt1 * (N * N));
            const float2* Cn = (const float2*)(C + bt1 * (P * N));
            const float2* Bn = (const float2*)(Bm + bt1 * (N * M));
            for (int i2 = pt; i2 < 512; i2 += 480) {
                int rr = i2 >> 4, c2 = i2 & 15;
                *(float2*)(sA[nxt] + rr * MA + 2 * c2) = An[i2];
            }
            if (pt < 256) {
                int rr = pt >> 4, c2 = pt & 15;
                *(float2*)(sC[nxt] + rr * MA + 2 * c2) = Cn[pt];
            }
            if (pt < 128) ((float2*)sB[nxt])[pt] = Bn[pt];
            if (pt < P) sy[nxt][pt] = Y[bt1 * P + pt];
            else if (pt < P + M) su[nxt][pt - P] = U[bt1 * M + (pt - P)];
        }
        __syncthreads();

        // ===== R4: Sf = Sigp - 0.5*(X^T CSp + CSp^T X) (2x2, fused sym) | mu_f
        if (tid < 256) {
            const int r0 = (tid >> 4) * 2, c0 = (tid & 15) * 2;
            float2 p0 = *(const float2*)(sSigp + r0 * MA + c0);
            float2 p1 = *(const float2*)(sSigp + (r0 + 1) * MA + c0);
            float m00 = 0, m01 = 0, m10 = 0, m11 = 0;
            #pragma unroll
            for (int j = 0; j < P; j++) {
                float2 xr = *(const float2*)(sX + j * MA + r0);
                float2 zr = *(const float2*)(sCSp + j * MA + r0);
                float2 xc = *(const float2*)(sX + j * MA + c0);
                float2 zc = *(const float2*)(sCSp + j * MA + c0);
                m00 += xr.x * zc.x + zr.x * xc.x;
                m01 += xr.x * zc.y + zr.x * xc.y;
                m10 += xr.y * zc.x + zr.y * xc.x;
                m11 += xr.y * zc.y + zr.y * xc.y;
            }
            float v00 = p0.x - 0.5f * m00, v01 = p0.y - 0.5f * m01;
            float v10 = p1.x - 0.5f * m10, v11 = p1.y - 0.5f * m11;
            *(float2*)(sSig + r0 * MA + c0) = make_float2(v00, v01);
            *(float2*)(sSig + (r0 + 1) * MA + c0) = make_float2(v10, v11);
            float* gf = g_Sigf + (bt << 10);
            *(float2*)(gf + r0 * 32 + c0) = make_float2(v00, v01);
            *(float2*)(gf + (r0 + 1) * 32 + c0) = make_float2(v10, v11);
        } else if (tid < 288) {
            const int i = tid - 256;
            float s = smup[i];
            #pragma unroll
            for (int j = 0; j < P; j++) s += sX[j * MA + i] * sd[j];
            smu[i] = s;
            g_muf[bt * N + i] = s;
        }
        __syncthreads();
    }
}

// =====================================================================
// Kernel 2: per (b,t) compute X_t = J_t^T, M_t, c_t. grid (127, 64), 128 thr.
// =====================================================================
__global__ __launch_bounds__(128) void k_J2(const float* __restrict__ A)
{
    const int t = blockIdx.x;
    const int b = blockIdx.y;
    const size_t bt = (size_t)b * T + t;
    const int tid = threadIdx.x;

    __shared__ __align__(16) float sA[N * MA], sSf[N * MA], sSp[N * MA];
    __shared__ __align__(16) float sG[N * MA], sXs[N * MA];
    __shared__ float smf[N], smp[N];

    {
        const float2* Ab = (const float2*)(A + bt * (N * N));
        const float2* gf = (const float2*)(g_Sigf + (bt << 10));
        const float2* gp = (const float2*)(g_Sigp + ((bt + 1) << 10));
        for (int i2 = tid; i2 < 512; i2 += 128) {
            int r = i2 >> 4, c = (i2 & 15) * 2;
            *(float2*)(sA + r * MA + c) = Ab[i2];
            *(float2*)(sSf + r * MA + c) = gf[i2];
            *(float2*)(sSp + r * MA + c) = gp[i2];
        }
        if (tid < N) {
            smf[tid] = g_muf[bt * N + tid];
            smp[tid] = g_mup[(bt + 1) * N + tid];
        }
    }
    __syncthreads();

    #pragma unroll
    for (int s = 0; s < 2; s++) {
        const int id = tid + s * 128;
        const int r0 = (id >> 4) * 2, c0 = (id & 15) * 2;
        const float2* Xr0 = (const float2*)(sA + r0 * MA);
        const float2* Xr1 = (const float2*)(sA + (r0 + 1) * MA);
        float a00 = 0, a01 = 0, a10 = 0, a11 = 0;
        #pragma unroll
        for (int k2 = 0; k2 < 16; k2++) {
            float2 x0 = Xr0[k2], x1 = Xr1[k2];
            float2 y0 = *(const float2*)(sSf + (2 * k2) * MA + c0);
            float2 y1 = *(const float2*)(sSf + (2 * k2 + 1) * MA + c0);
            a00 += x0.x * y0.x + x0.y * y1.x;  a01 += x0.x * y0.y + x0.y * y1.y;
            a10 += x1.x * y0.x + x1.y * y1.x;  a11 += x1.x * y0.y + x1.y * y1.y;
        }
        *(float2*)(sG + r0 * MA + c0) = make_float2(a00, a01);
        *(float2*)(sG + (r0 + 1) * MA + c0) = make_float2(a10, a11);
    }
    __syncthreads();

    if (tid < 32) {
        const int c = tid;
        float Sc[N], Gc[N];
        #pragma unroll
        for (int rr = 0; rr < N; rr++) {
            Sc[rr] = sSp[rr * MA + c];
            Gc[rr] = sG[rr * MA + c];
        }
        #pragma unroll
        for (int j = 0; j < N; j++) {
            float fj = __shfl_sync(0xffffffffu, Sc[j], j);
            float pinv = 1.0f / fj;
            Sc[j] *= pinv;
            Gc[j] *= pinv;
            float scj = Sc[j], gcj = Gc[j];
            #pragma unroll
            for (int rr = 0; rr < N; rr++) {
                if (rr != j) {
                    float f = __shfl_sync(0xffffffffu, Sc[rr], j);
                    Sc[rr] -= f * scj;
                    Gc[rr] -= f * gcj;
                }
            }
        }
        #pragma unroll
        for (int rr = 0; rr < N; rr++) sXs[rr * MA + c] = Gc[rr];
    }
    __syncthreads();

    const size_t jidx = (size_t)b * (T - 1) + t;

    if (tid < N) {
        float s = smf[tid];
        #pragma unroll
        for (int k = 0; k < N; k++) s -= sXs[k * MA + tid] * smp[k];
        g_c[jidx * N + tid] = s;
    }
    {
        float2* gj = (float2*)(g_J + jidx * (N * N));
        for (int i2 = tid; i2 < 512; i2 += 128) {
            int r = i2 >> 4, c = (i2 & 15) * 2;
            gj[i2] = *(const float2*)(sXs + r * MA + c);
        }
    }
    {
        float* gm = g_M + jidx * (N * N);
        #pragma unroll
        for (int s = 0; s < 2; s++) {
            const int id = tid + s * 128;
            const int r0 = (id >> 4) * 2, c0 = (id & 15) * 2;
            float2 f0 = *(const float2*)(sSf + r0 * MA + c0);
            float2 f1 = *(const float2*)(sSf + (r0 + 1) * MA + c0);
            float a00 = f0.x, a01 = f0.y, a10 = f1.x, a11 = f1.y;
            #pragma unroll
            for (int k = 0; k < N; k++) {
                float x0 = sXs[k * MA + r0], x1 = sXs[k * MA + r0 + 1];
                float2 g = *(const float2*)(sG + k * MA + c0);
                a00 -= x0 * g.x;  a01 -= x0 * g.y;
                a10 -= x1 * g.x;  a11 -= x1 * g.y;
            }
            *(float2*)(gm + r0 * 32 + c0) = make_float2(a00, a01);
            *(float2*)(gm + (r0 + 1) * 32 + c0) = make_float2(a10, a11);
        }
    }
}

// =====================================================================
// Kernel 3 (Phase A): compose chunk operators. grid (16, 64), 256 thr.
// Register-prefetched next-t X/M/c.
// =====================================================================
__global__ __launch_bounds__(256) void k_scanA()
{
    const int k = blockIdx.x, b = blockIdx.y;
    const int t_lo = CHS * k;
    const int t_hi = (k == NCH - 1) ? (T - 2) : (CHS * k + CHS - 1);
    const int tid = threadIdx.x;

    __shared__ __align__(16) float sXO[N * MA], sMO[N * MA];
    __shared__ __align__(16) float sXt[2][N * MA], sMt[2][N * MA];
    __shared__ __align__(16) float sW[N * MA], sXN[N * MA];
    __shared__ float scO[N], sct[2][N], scN[N];

    const int r0 = (tid >> 4) * 2, c0 = (tid & 15) * 2;
    const int ra = tid >> 4, ca = (tid & 15) * 2;
    const int rb = ra + 16;

    {
        const size_t base = (size_t)b * (T - 1) + t_hi;
        const float2* gx = (const float2*)(g_J + base * (N * N));
        const float2* gm = (const float2*)(g_M + base * (N * N));
        for (int i2 = tid; i2 < 512; i2 += 256) {
            int r = i2 >> 4, c = (i2 & 15) * 2;
            *(float2*)(sXO + r * MA + c) = gx[i2];
            *(float2*)(sMO + r * MA + c) = gm[i2];
        }
        if (tid < N) scO[tid] = g_c[base * N + tid];
    }

    float2 pX0, pX1, pM0, pM1;
    float pc = 0.f;
    if (t_hi - 1 >= t_lo) {
        const size_t base = (size_t)b * (T - 1) + (t_hi - 1);
        const float2* gx = (const float2*)(g_J + base * (N * N));
        const float2* gm = (const float2*)(g_M + base * (N * N));
        pX0 = gx[tid];  pX1 = gx[tid + 256];
        pM0 = gm[tid];  pM1 = gm[tid + 256];
        if (tid < N) pc = g_c[base * N + tid];
    }
    __syncthreads();

    for (int t = t_hi - 1; t >= t_lo; t--) {
        const int buf = (t_hi - 1 - t) & 1;
        *(float2*)(sXt[buf] + ra * MA + ca) = pX0;
        *(float2*)(sXt[buf] + rb * MA + ca) = pX1;
        *(float2*)(sMt[buf] + ra * MA + ca) = pM0;
        *(float2*)(sMt[buf] + rb * MA + ca) = pM1;
        if (tid < N) sct[buf][tid] = pc;
        if (t > t_lo) {
            const size_t base = (size_t)b * (T - 1) + (t - 1);
            const float2* gx = (const float2*)(g_J + base * (N * N));
            const float2* gm = (const float2*)(g_M + base * (N * N));
            pX0 = gx[tid];  pX1 = gx[tid + 256];
            pM0 = gm[tid];  pM1 = gm[tid + 256];
            if (tid < N) pc = g_c[base * N + tid];
        }
        __syncthreads();

        const float* Xt = sXt[buf];
        const float* Mt = sMt[buf];

        {
            const float2* Mr0 = (const float2*)(sMO + r0 * MA);
            const float2* Mr1 = (const float2*)(sMO + (r0 + 1) * MA);
            const float2* Or0 = (const float2*)(sXO + r0 * MA);
            const float2* Or1 = (const float2*)(sXO + (r0 + 1) * MA);
            float w00 = 0, w01 = 0, w10 = 0, w11 = 0;
            float x00 = 0, x01 = 0, x10 = 0, x11 = 0;
            #pragma unroll
            for (int k2 = 0; k2 < 16; k2++) {
                float2 y0 = *(const float2*)(Xt + (2 * k2) * MA + c0);
                float2 y1 = *(const float2*)(Xt + (2 * k2 + 1) * MA + c0);
                float2 m0 = Mr0[k2], m1 = Mr1[k2];
                float2 o0 = Or0[k2], o1 = Or1[k2];
                w00 += m0.x * y0.x + m0.y * y1.x;  w01 += m0.x * y0.y + m0.y * y1.y;
                w10 += m1.x * y0.x + m1.y * y1.x;  w11 += m1.x * y0.y + m1.y * y1.y;
                x00 += o0.x * y0.x + o0.y * y1.x;  x01 += o0.x * y0.y + o0.y * y1.y;
                x10 += o1.x * y0.x + o1.y * y1.x;  x11 += o1.x * y0.y + o1.y * y1.y;
            }
            *(float2*)(sW + r0 * MA + c0) = make_float2(w00, w01);
            *(float2*)(sW + (r0 + 1) * MA + c0) = make_float2(w10, w11);
            *(float2*)(sXN + r0 * MA + c0) = make_float2(x00, x01);
            *(float2*)(sXN + (r0 + 1) * MA + c0) = make_float2(x10, x11);
        }
        if (tid < N) {
            float s = sct[buf][tid];
            #pragma unroll
            for (int j = 0; j < N; j++) s += Xt[j * MA + tid] * scO[j];
            scN[tid] = s;
        }
        __syncthreads();

        {
            float2 f0 = *(const float2*)(Mt + r0 * MA + c0);
            float2 f1 = *(const float2*)(Mt + (r0 + 1) * MA + c0);
            float a00 = f0.x, a01 = f0.y, a10 = f1.x, a11 = f1.y;
            #pragma unroll
            for (int j = 0; j < N; j++) {
                float2 xj = *(const float2*)(Xt + j * MA + r0);
                float2 wj = *(const float2*)(sW + j * MA + c0);
                a00 += xj.x * wj.x;  a01 += xj.x * wj.y;
                a10 += xj.y * wj.x;  a11 += xj.y * wj.y;
            }
            *(float2*)(sMO + r0 * MA + c0) = make_float2(a00, a01);
            *(float2*)(sMO + (r0 + 1) * MA + c0) = make_float2(a10, a11);
            *(float2*)(sXO + r0 * MA + c0) = *(const float2*)(sXN + r0 * MA + c0);
            *(float2*)(sXO + (r0 + 1) * MA + c0) = *(const float2*)(sXN + (r0 + 1) * MA + c0);
        }
        if (tid < N) scO[tid] = scN[tid];
        __syncthreads();
    }

    {
        const size_t obase = (size_t)b * NCH + k;
        float2* gx = (float2*)(g_OX + obase * (N * N));
        float2* gm = (float2*)(g_OM + obase * (N * N));
        for (int i2 = tid; i2 < 512; i2 += 256) {
            int r = i2 >> 4, c = (i2 & 15) * 2;
            gx[i2] = *(const float2*)(sXO + r * MA + c);
            gm[i2] = *(const float2*)(sMO + r * MA + c);
        }
        if (tid < N) g_Oc[obase * N + tid] = scO[tid];
    }
}

// =====================================================================
// Kernel 4 (Phase B): boundary states per batch. grid 64, 256 thr.
// =====================================================================
__global__ __launch_bounds__(256) void k_scanB(float* __restrict__ out)
{
    const int b = blockIdx.x;
    const int tid = threadIdx.x;

    __shared__ __align__(16) float sS[N * MA], sX[N * MA], sMm[N * MA], sW[N * MA];
    __shared__ float smu[N], smuN[N], sc[N];

    const int r0 = (tid >> 4) * 2, c0 = (tid & 15) * 2;

    {
        const size_t btL = (size_t)b * T + (T - 1);
        const float2* gf = (const float2*)(g_Sigf + (btL << 10));
        float2* ge = (float2*)(g_eS + ((size_t)b * NCH + (NCH - 1)) * (N * N));
        for (int i2 = tid; i2 < 512; i2 += 256) {
            int r = i2 >> 4, c = (i2 & 15) * 2;
            float2 v = gf[i2];
            *(float2*)(sS + r * MA + c) = v;
            ge[i2] = v;
            float* o = out + (btL * N + r) * (N + 1) + 1 + c;
            o[0] = v.x; o[1] = v.y;
        }
        if (tid < N) {
            float v = g_muf[btL * N + tid];
            smu[tid] = v;
            g_emu[((size_t)b * NCH + (NCH - 1)) * N + tid] = v;
            out[(btL * N + tid) * (N + 1)] = v;
        }
    }
    __syncthreads();

    for (int k = NCH - 2; k >= 0; k--) {
        const size_t obase = (size_t)b * NCH + (k + 1);
        {
            const float2* gx = (const float2*)(g_OX + obase * (N * N));
            const float2* gm = (const float2*)(g_OM + obase * (N * N));
            for (int i2 = tid; i2 < 512; i2 += 256) {
                int r = i2 >> 4, c = (i2 & 15) * 2;
                *(float2*)(sX + r * MA + c) = gx[i2];
                *(float2*)(sMm + r * MA + c) = gm[i2];
            }
            if (tid < N) sc[tid] = g_Oc[obase * N + tid];
        }
        __syncthreads();

        {
            const float2* Sr0 = (const float2*)(sS + r0 * MA);
            const float2* Sr1 = (const float2*)(sS + (r0 + 1) * MA);
            float a00 = 0, a01 = 0, a10 = 0, a11 = 0;
            #pragma unroll
            for (int k2 = 0; k2 < 16; k2++) {
                float2 x0 = Sr0[k2], x1 = Sr1[k2];
                float2 y0 = *(const float2*)(sX + (2 * k2) * MA + c0);
                float2 y1 = *(const float2*)(sX + (2 * k2 + 1) * MA + c0);
                a00 += x0.x * y0.x + x0.y * y1.x;  a01 += x0.x * y0.y + x0.y * y1.y;
                a10 += x1.x * y0.x + x1.y * y1.x;  a11 += x1.x * y0.y + x1.y * y1.y;
            }
            *(float2*)(sW + r0 * MA + c0) = make_float2(a00, a01);
            *(float2*)(sW + (r0 + 1) * MA + c0) = make_float2(a10, a11);
        }
        if (tid < N) {
            float s = sc[tid];
            #pragma unroll
            for (int j = 0; j < N; j++) s += sX[j * MA + tid] * smu[j];
            smuN[tid] = s;
        }
        __syncthreads();

        {
            float2 f0 = *(const float2*)(sMm + r0 * MA + c0);
            float2 f1 = *(const float2*)(sMm + (r0 + 1) * MA + c0);
            float a00 = f0.x, a01 = f0.y, a10 = f1.x, a11 = f1.y;
            #pragma unroll
            for (int j = 0; j < N; j++) {
                float2 xj = *(const float2*)(sX + j * MA + r0);
                float2 wj = *(const float2*)(sW + j * MA + c0);
                a00 += xj.x * wj.x;  a01 += xj.x * wj.y;
                a10 += xj.y * wj.x;  a11 += xj.y * wj.y;
            }
            *(float2*)(sS + r0 * MA + c0) = make_float2(a00, a01);
            *(float2*)(sS + (r0 + 1) * MA + c0) = make_float2(a10, a11);
            float* ge = g_eS + ((size_t)b * NCH + k) * (N * N);
            *(float2*)(ge + r0 * 32 + c0) = make_float2(a00, a01);
            *(float2*)(ge + (r0 + 1) * 32 + c0) = make_float2(a10, a11);
        }
        if (tid < N) {
            smu[tid] = smuN[tid];
            g_emu[((size_t)b * NCH + k) * N + tid] = smuN[tid];
        }
        __syncthreads();
    }
}

// =====================================================================
// Kernel 5 (Phase C): per-chunk backward recursion. grid (16, 64), 256 thr.
// Register-prefetched like k_scanA.
// =====================================================================
__global__ __launch_bounds__(256) void k_scanC(float* __restrict__ out)
{
    const int k = blockIdx.x, b = blockIdx.y;
    const int t_lo = CHS * k;
    const int t_hi = (k == NCH - 1) ? (T - 2) : (CHS * k + CHS - 1);
    const int tid = threadIdx.x;

    __shared__ __align__(16) float sS[N * MA], sW[N * MA];
    __shared__ __align__(16) float sX[2][N * MA], sMm[2][N * MA];
    __shared__ float smu[N], smuN[N], sc[2][N];

    const int r0 = (tid >> 4) * 2, c0 = (tid & 15) * 2;
    const int ra = tid >> 4, ca = (tid & 15) * 2;
    const int rb = ra + 16;

    {
        const size_t ebase = (size_t)b * NCH + k;
        const float2* ge = (const float2*)(g_eS + ebase * (N * N));
        for (int i2 = tid; i2 < 512; i2 += 256) {
            int r = i2 >> 4, c = (i2 & 15) * 2;
            *(float2*)(sS + r * MA + c) = ge[i2];
        }
        if (tid < N) smu[tid] = g_emu[ebase * N + tid];
    }

    float2 pX0, pX1, pM0, pM1;
    float pc = 0.f;
    {
        const size_t base = (size_t)b * (T - 1) + t_hi;
        const float2* gx = (const float2*)(g_J + base * (N * N));
        const float2* gm = (const float2*)(g_M + base * (N * N));
        pX0 = gx[tid];  pX1 = gx[tid + 256];
        pM0 = gm[tid];  pM1 = gm[tid + 256];
        if (tid < N) pc = g_c[base * N + tid];
    }
    __syncthreads();

    for (int t = t_hi; t >= t_lo; t--) {
        const int buf = (t_hi - t) & 1;
        const size_t bt = (size_t)b * T + t;
        *(float2*)(sX[buf] + ra * MA + ca) = pX0;
        *(float2*)(sX[buf] + rb * MA + ca) = pX1;
        *(float2*)(sMm[buf] + ra * MA + ca) = pM0;
        *(float2*)(sMm[buf] + rb * MA + ca) = pM1;
        if (tid < N) sc[buf][tid] = pc;
        if (t > t_lo) {
            const size_t base = (size_t)b * (T - 1) + (t - 1);
            const float2* gx = (const float2*)(g_J + base * (N * N));
            const float2* gm = (const float2*)(g_M + base * (N * N));
            pX0 = gx[tid];  pX1 = gx[tid + 256];
            pM0 = gm[tid];  pM1 = gm[tid + 256];
            if (tid < N) pc = g_c[base * N + tid];
        }
        __syncthreads();

        const float* Xb = sX[buf];
        const float* Mb = sMm[buf];

        {
            const float2* Sr0 = (const float2*)(sS + r0 * MA);
            const float2* Sr1 = (const float2*)(sS + (r0 + 1) * MA);
            float a00 = 0, a01 = 0, a10 = 0, a11 = 0;
            #pragma unroll
            for (int k2 = 0; k2 < 16; k2++) {
                float2 x0 = Sr0[k2], x1 = Sr1[k2];
                float2 y0 = *(const float2*)(Xb + (2 * k2) * MA + c0);
                float2 y1 = *(const float2*)(Xb + (2 * k2 + 1) * MA + c0);
                a00 += x0.x * y0.x + x0.y * y1.x;  a01 += x0.x * y0.y + x0.y * y1.y;
                a10 += x1.x * y0.x + x1.y * y1.x;  a11 += x1.x * y0.y + x1.y * y1.y;
            }
            *(float2*)(sW + r0 * MA + c0) = make_float2(a00, a01);
            *(float2*)(sW + (r0 + 1) * MA + c0) = make_float2(a10, a11);
        }
        if (tid < N) {
            float s = sc[buf][tid];
            #pragma unroll
            for (int j = 0; j < N; j++) s += Xb[j * MA + tid] * smu[j];
            smuN[tid] = s;
        }
        __syncthreads();

        {
            float2 f0 = *(const float2*)(Mb + r0 * MA + c0);
            float2 f1 = *(const float2*)(Mb + (r0 + 1) * MA + c0);
            float a00 = f0.x, a01 = f0.y, a10 = f1.x, a11 = f1.y;
            #pragma unroll
            for (int j = 0; j < N; j++) {
                float2 xj = *(const float2*)(Xb + j * MA + r0);
                float2 wj = *(const float2*)(sW + j * MA + c0);
                a00 += xj.x * wj.x;  a01 += xj.x * wj.y;
                a10 += xj.y * wj.x;  a11 += xj.y * wj.y;
            }
            *(float2*)(sS + r0 * MA + c0) = make_float2(a00, a01);
            *(float2*)(sS + (r0 + 1) * MA + c0) = make_float2(a10, a11);
            float* o = out + (bt * N + r0) * (N + 1) + 1 + c0;
            o[0] = a00; o[1] = a01;
            o[N + 1] = a10; o[N + 2] = a11;
        }
        if (tid < N) {
            smu[tid] = smuN[tid];
            out[(bt * N + tid) * (N + 1)] = smuN[tid];
        }
        __syncthreads();
    }
}

extern "C" void kernel_launch(void* const* d_in, const int* in_sizes, int n_in,
                              void* d_out, int out_size) {
    (void)in_sizes; (void)n_in; (void)out_size;
    const float* Y   = (const float*)d_in[0];
    const float* U   = (const float*)d_in[1];
    const float* A   = (const float*)d_in[2];
    const float* Bm  = (const float*)d_in[3];
    const float* C   = (const float*)d_in[4];
    const float* mu0 = (const float*)d_in[5];
    const float* S0  = (const float*)d_in[6];
    float* out = (float*)d_out;

    k_fwd<<<BATCH, NTF>>>(Y, U, A, Bm, C, mu0, S0);
    k_J2<<<dim3(T - 1, BATCH), 128>>>(A);
    k_scanA<<<dim3(NCH, BATCH), 256>>>();
    k_scanB<<<BATCH, 256>>>(out);
    k_scanC<<<dim3(NCH, BATCH), 256>>>(out);
}